// round 13
// baseline (speedup 1.0000x reference)
#include <cuda_runtime.h>
#include <cuda_fp16.h>
#include <mma.h>
#include <cstdint>

using namespace nvcuda;

#define NN   50000
#define NE   20000
#define NNZV 1600000
#define CH   1024   // concat(4) * hid(256)
#define CIN  256
#define COUT 40
#define PADE 192    // max edge degree slot count (Poisson(80) max ~120)
#define PADN 96     // max node degree slot count (Poisson(32) max ~58)

// fused fill+cvt kernel geometry
#define FILL_BLOCKS ((NNZV + 255) / 256)          // 6250 blocks of fill work
#define CVT_X_T  12800000                          // x: 51.2M halves / 4 per thread
#define CVT_W1_T (CVT_X_T + 65536)                 // W1: 262144 floats / 4
#define CVT_W2_T (CVT_W1_T + 49152)                // W2 padded: 1024*48 elems
#define CVT_BLOCKS ((CVT_W2_T + 255) / 256)        // 50448

// ---------------- device scratch (static; no allocations) ----------------
__device__ int   g_cnt_v[NN];
__device__ int   g_cnt_e[NE];
__device__ int   g_elist[NE * PADE];   // nodes grouped by edge (padded rows)
__device__ int   g_nlist[NN * PADN];   // edges grouped by node (padded rows)
__device__ float g_t1[NE];
__device__ __half g_xh[51200000];      // [4][NN][256] fp16 (UNSCALED)
__device__ __half g_W1h[262144];       // [4][256][256] fp16
__device__ __half g_W2h[49152];        // [1024][48] fp16 (N padded 40->48)
__device__ __half g_zh [20480000];     // [NE][CH] fp16
__device__ __half g_z2h[20480000];     // [NE][CH] fp16
__device__ __half g_hiddenh[51200000]; // [NN][CH] fp16
__device__ __half g_gvh[2000000];      // [NN][COUT] fp16 (prescaled by dv_is)
__device__ __half g_ef2h[800000];      // [NE][COUT] fp16

__device__ __forceinline__ float dvis_of(int c)  { return (c > 0) ? rsqrtf((float)c) : 0.f; }
__device__ __forceinline__ float deinv_of(int c) { return (c > 0) ? (1.f / (float)c) : 0.f; }

// ---------------- init ----------------
__global__ void k_zero() {
    int i = blockIdx.x * blockDim.x + threadIdx.x;
    if (i < NN) g_cnt_v[i] = 0;
    if (i < NE) g_cnt_e[i] = 0;
}

// ---------------- fused: CSR fill (atomic slot alloc) + fp16 conversions ----------------
// Blocks [0, FILL_BLOCKS): one-pass CSR build (L2-atomic bound).
// Blocks [FILL_BLOCKS, FILL_BLOCKS+CVT_BLOCKS): x/W1/W2 -> fp16 (DRAM bound).
// The two phases have no data dependency (x is stored UNSCALED) and stress
// disjoint resources, so co-scheduling overlaps them.
__global__ void k_fillcvt(const int* __restrict__ ni, const int* __restrict__ ei, int nnz,
                          const float* __restrict__ x, const float* __restrict__ W1,
                          const float* __restrict__ W2) {
    int blk = blockIdx.x;
    if (blk < FILL_BLOCKS) {
        int i = blk * 256 + threadIdx.x;
        if (i < nnz) {
            int v = ni[i], e = ei[i];
            int p = atomicAdd(&g_cnt_e[e], 1);
            if (p < PADE) g_elist[e * PADE + p] = v;
            int q = atomicAdd(&g_cnt_v[v], 1);
            if (q < PADN) g_nlist[v * PADN + q] = e;
        }
    } else {
        int tid = (blk - FILL_BLOCKS) * 256 + threadIdx.x;
        if (tid < CVT_X_T) {
            int lin = tid * 4;
            float4 xv = *(const float4*)(x + lin);
            __half2 h0 = __floats2half2_rn(xv.x, xv.y);
            __half2 h1 = __floats2half2_rn(xv.z, xv.w);
            uint2 o;
            o.x = *(unsigned*)&h0;
            o.y = *(unsigned*)&h1;
            *(uint2*)&g_xh[lin] = o;
        } else if (tid < CVT_W1_T) {
            int lin = (tid - CVT_X_T) * 4;
            float4 v = *(const float4*)(W1 + lin);
            __half2 h0 = __floats2half2_rn(v.x, v.y);
            __half2 h1 = __floats2half2_rn(v.z, v.w);
            uint2 o; o.x = *(unsigned*)&h0; o.y = *(unsigned*)&h1;
            *(uint2*)&g_W1h[lin] = o;
        } else if (tid < CVT_W2_T) {
            int j2 = tid - CVT_W1_T;
            int k = j2 / 48, j = j2 % 48;
            float v = (j < COUT) ? W2[k * COUT + j] : 0.f;
            g_W2h[j2] = __float2half_rn(v);
        }
    }
}

// ---------------- pass A: zh[e][:] = de_inv[e] * sum_{v in e} dvis[v]*xh[v][:]; also t1[e] ----------------
__global__ void k_passA() {
    __shared__ int   svv[128];
    __shared__ float sww[128];
    int e = blockIdx.x, t = threadIdx.x;
    int beg = e * PADE;
    int cnte = g_cnt_e[e];
    int deg = min(cnte, PADE);
    int b = t >> 5, c = (t & 31) * 8;
    const __half* xb = g_xh + (size_t)b * NN * CIN + c;
    float a0 = 0.f, a1 = 0.f, a2 = 0.f, a3 = 0.f, a4 = 0.f, a5 = 0.f, a6 = 0.f, a7 = 0.f;
    float at = 0.f;
    for (int base = 0; base < deg; base += 128) {
        int m = min(128, deg - base);
        __syncthreads();
        if (t < m) {
            int v = g_elist[beg + base + t];
            svv[t] = v;
            sww[t] = rsqrtf((float)g_cnt_v[v]);   // v in list => cnt >= 1
        }
        __syncthreads();
        #pragma unroll 8
        for (int i = 0; i < m; i++) {
            float w = sww[i];
            at += w;
            uint4 rv = *(const uint4*)(xb + (size_t)svv[i] * CIN);
            float2 f0 = __half22float2(*(__half2*)&rv.x);
            float2 f1 = __half22float2(*(__half2*)&rv.y);
            float2 f2 = __half22float2(*(__half2*)&rv.z);
            float2 f3 = __half22float2(*(__half2*)&rv.w);
            a0 = fmaf(w, f0.x, a0); a1 = fmaf(w, f0.y, a1);
            a2 = fmaf(w, f1.x, a2); a3 = fmaf(w, f1.y, a3);
            a4 = fmaf(w, f2.x, a4); a5 = fmaf(w, f2.y, a5);
            a6 = fmaf(w, f3.x, a6); a7 = fmaf(w, f3.y, a7);
        }
    }
    float sc = deinv_of(cnte);
    if (t == 0) g_t1[e] = sc * at;
    __half2 h0 = __floats2half2_rn(sc * a0, sc * a1);
    __half2 h1 = __floats2half2_rn(sc * a2, sc * a3);
    __half2 h2 = __floats2half2_rn(sc * a4, sc * a5);
    __half2 h3 = __floats2half2_rn(sc * a6, sc * a7);
    uint4 o;
    o.x = *(unsigned*)&h0; o.y = *(unsigned*)&h1;
    o.z = *(unsigned*)&h2; o.w = *(unsigned*)&h3;
    *(uint4*)&g_zh[(size_t)e * CH + t * 8] = o;
}

// ---------------- edge GEMM via wmma: z2h = zh @ blockdiag(W1h[b]) ----------------
// block: 256 thr (8 warps, 4x2), tile M=128 x N=128, K=256 in panels of 64.
__global__ void k_egemm() {
    __shared__ __align__(16) union {
        struct { __half A[128][72]; __half B[64][136]; } in;  // 18432 + 17408 = 35840
        float Cf[8][16 * 68];                                  // 34816
    } sm;
    int t = threadIdx.x;
    int warp = t >> 5, lane = t & 31;
    int wm = warp >> 1, wn = warp & 1;
    int b = blockIdx.z;
    int row0 = blockIdx.x * 128;
    int col0 = blockIdx.y * 128;

    wmma::fragment<wmma::accumulator, 16, 16, 16, float> acc[2][4];
    #pragma unroll
    for (int i = 0; i < 2; i++)
        #pragma unroll
        for (int j = 0; j < 4; j++) wmma::fill_fragment(acc[i][j], 0.f);

    for (int kp = 0; kp < 256; kp += 64) {
        __syncthreads();
        #pragma unroll
        for (int i = 0; i < 4; i++) {   // A: 128x64 halfs = 1024 uint4 groups
            int g = t + 256 * i;
            int row = g >> 3, gc = (g & 7) * 8;
            int r = row0 + row;
            uint4 val = make_uint4(0u, 0u, 0u, 0u);
            if (r < NE) val = *(const uint4*)&g_zh[(size_t)r * CH + b * 256 + kp + gc];
            *(uint4*)&sm.in.A[row][gc] = val;
        }
        #pragma unroll
        for (int i = 0; i < 4; i++) {   // B: 64x128 halfs = 1024 uint4 groups
            int g = t + 256 * i;
            int row = g >> 4, gc = (g & 15) * 8;
            *(uint4*)&sm.in.B[row][gc] =
                *(const uint4*)&g_W1h[b * 65536 + (kp + row) * 256 + col0 + gc];
        }
        __syncthreads();
        #pragma unroll
        for (int ks = 0; ks < 4; ks++) {
            wmma::fragment<wmma::matrix_a, 16, 16, 16, __half, wmma::row_major> af[2];
            wmma::load_matrix_sync(af[0], &sm.in.A[wm * 32][ks * 16], 72);
            wmma::load_matrix_sync(af[1], &sm.in.A[wm * 32 + 16][ks * 16], 72);
            #pragma unroll
            for (int j = 0; j < 4; j++) {
                wmma::fragment<wmma::matrix_b, 16, 16, 16, __half, wmma::row_major> bf;
                wmma::load_matrix_sync(bf, &sm.in.B[ks * 16][wn * 64 + j * 16], 136);
                wmma::mma_sync(acc[0][j], af[0], bf, acc[0][j]);
                wmma::mma_sync(acc[1][j], af[1], bf, acc[1][j]);
            }
        }
    }
    __syncthreads();   // union reuse: all mma smem reads complete
    // two-phase per-warp epilogue (16 rows at a time) to fit smem
    #pragma unroll
    for (int i = 0; i < 2; i++) {
        #pragma unroll
        for (int j = 0; j < 4; j++)
            wmma::store_matrix_sync(&sm.Cf[warp][j * 16], acc[i][j], 68, wmma::mem_row_major);
        __syncwarp();
        int row = lane >> 1;
        int colh = (lane & 1) * 32;
        int gr = row0 + wm * 32 + i * 16 + row;
        if (gr < NE) {
            size_t base = (size_t)gr * CH + b * 256 + col0 + wn * 64 + colh;
            const float* cr = &sm.Cf[warp][row * 68 + colh];
            #pragma unroll
            for (int g4 = 0; g4 < 4; g4++) {
                float4 v0 = *(const float4*)&cr[g4 * 8];
                float4 v1 = *(const float4*)&cr[g4 * 8 + 4];
                __half2 h0 = __floats2half2_rn(v0.x, v0.y);
                __half2 h1 = __floats2half2_rn(v0.z, v0.w);
                __half2 h2 = __floats2half2_rn(v1.x, v1.y);
                __half2 h3 = __floats2half2_rn(v1.z, v1.w);
                uint4 o;
                o.x = *(unsigned*)&h0; o.y = *(unsigned*)&h1;
                o.z = *(unsigned*)&h2; o.w = *(unsigned*)&h3;
                *(uint4*)&g_z2h[base + g4 * 8] = o;
            }
        }
        __syncwarp();
    }
}

// ---------------- pass B: hiddenh[v][:] = relu(dv_is[v]*sum z2h + s[v]*b1[:]); s inline ----------------
__global__ void k_passB(const float* __restrict__ b1) {
    __shared__ int   see[128];
    __shared__ float st1[128];
    int v = blockIdx.x, t = threadIdx.x;
    int beg = v * PADN;
    int cntv = g_cnt_v[v];
    int deg = min(cntv, PADN);
    const __half* zb = g_z2h + t * 8;
    float a0 = 0.f, a1 = 0.f, a2 = 0.f, a3 = 0.f, a4 = 0.f, a5 = 0.f, a6 = 0.f, a7 = 0.f;
    float at = 0.f;
    for (int base = 0; base < deg; base += 128) {
        int m = min(128, deg - base);
        __syncthreads();
        if (t < m) {
            int ee = g_nlist[beg + base + t];
            see[t] = ee;
            st1[t] = g_t1[ee];
        }
        __syncthreads();
        #pragma unroll 8
        for (int i = 0; i < m; i++) {
            at += st1[i];
            uint4 rv = *(const uint4*)(zb + (size_t)see[i] * CH);
            float2 f0 = __half22float2(*(__half2*)&rv.x);
            float2 f1 = __half22float2(*(__half2*)&rv.y);
            float2 f2 = __half22float2(*(__half2*)&rv.z);
            float2 f3 = __half22float2(*(__half2*)&rv.w);
            a0 += f0.x; a1 += f0.y; a2 += f1.x; a3 += f1.y;
            a4 += f2.x; a5 += f2.y; a6 += f3.x; a7 += f3.y;
        }
    }
    float w = dvis_of(cntv);
    float sv = w * at;   // s[v] = dvis[v] * sum t1
    int c = t * 8;
    float4 bb0 = *(const float4*)&b1[c];
    float4 bb1 = *(const float4*)&b1[c + 4];
    float r0 = fmaxf(w * a0 + sv * bb0.x, 0.f);
    float r1 = fmaxf(w * a1 + sv * bb0.y, 0.f);
    float r2 = fmaxf(w * a2 + sv * bb0.z, 0.f);
    float r3 = fmaxf(w * a3 + sv * bb0.w, 0.f);
    float r4 = fmaxf(w * a4 + sv * bb1.x, 0.f);
    float r5 = fmaxf(w * a5 + sv * bb1.y, 0.f);
    float r6 = fmaxf(w * a6 + sv * bb1.z, 0.f);
    float r7 = fmaxf(w * a7 + sv * bb1.w, 0.f);
    __half2 h0 = __floats2half2_rn(r0, r1);
    __half2 h1 = __floats2half2_rn(r2, r3);
    __half2 h2 = __floats2half2_rn(r4, r5);
    __half2 h3 = __floats2half2_rn(r6, r7);
    uint4 o;
    o.x = *(unsigned*)&h0; o.y = *(unsigned*)&h1;
    o.z = *(unsigned*)&h2; o.w = *(unsigned*)&h3;
    *(uint4*)&g_hiddenh[(size_t)v * CH + c] = o;
}

// ---------------- GEMM2 via wmma: gvh = fp16(dvis * (hiddenh @ W2h + b2)) ----------------
__global__ void k_gemm2(const float* __restrict__ b2) {
    __shared__ __align__(16) union {
        struct { __half A[128][72]; __half B[64][56]; } in;   // 18432 + 7168
        float C[8][832];                                       // 26624
    } sm;
    int t = threadIdx.x;
    int warp = t >> 5, lane = t & 31;
    int row0 = blockIdx.x * 128;

    wmma::fragment<wmma::accumulator, 16, 16, 16, float> acc[3];
    #pragma unroll
    for (int j = 0; j < 3; j++) wmma::fill_fragment(acc[j], 0.f);

    for (int kp = 0; kp < CH; kp += 64) {
        __syncthreads();
        #pragma unroll
        for (int i = 0; i < 4; i++) {   // A: 128x64
            int g = t + 256 * i;
            int row = g >> 3, gc = (g & 7) * 8;
            int r = row0 + row;
            uint4 val = make_uint4(0u, 0u, 0u, 0u);
            if (r < NN) val = *(const uint4*)&g_hiddenh[(size_t)r * CH + kp + gc];
            *(uint4*)&sm.in.A[row][gc] = val;
        }
        #pragma unroll
        for (int i = 0; i < 2; i++) {   // B: 64x48 halfs = 384 uint4 groups
            int g = t + 256 * i;
            if (g < 384) {
                int row = g / 6, gc = (g % 6) * 8;
                *(uint4*)&sm.in.B[row][gc] = *(const uint4*)&g_W2h[(kp + row) * 48 + gc];
            }
        }
        __syncthreads();
        #pragma unroll
        for (int ks = 0; ks < 4; ks++) {
            wmma::fragment<wmma::matrix_a, 16, 16, 16, __half, wmma::row_major> af;
            wmma::load_matrix_sync(af, &sm.in.A[warp * 16][ks * 16], 72);
            #pragma unroll
            for (int j = 0; j < 3; j++) {
                wmma::fragment<wmma::matrix_b, 16, 16, 16, __half, wmma::row_major> bf;
                wmma::load_matrix_sync(bf, &sm.in.B[ks * 16][j * 16], 56);
                wmma::mma_sync(acc[j], af, bf, acc[j]);
            }
        }
    }
    __syncthreads();
    #pragma unroll
    for (int j = 0; j < 3; j++)
        wmma::store_matrix_sync(&sm.C[warp][j * 16], acc[j], 52, wmma::mem_row_major);
    __syncwarp();
    if (lane < 16) {
        int gr = row0 + warp * 16 + lane;
        if (gr < NN) {
            float w = dvis_of(g_cnt_v[gr]);
            const float* cr = &sm.C[warp][lane * 52];
            #pragma unroll
            for (int g4 = 0; g4 < 10; g4++) {
                float4 c0 = *(const float4*)&cr[g4 * 4];
                float4 d0 = *(const float4*)&b2[g4 * 4];
                __half2 h0 = __floats2half2_rn(w * (c0.x + d0.x), w * (c0.y + d0.y));
                __half2 h1 = __floats2half2_rn(w * (c0.z + d0.z), w * (c0.w + d0.w));
                uint2 o;
                o.x = *(unsigned*)&h0; o.y = *(unsigned*)&h1;
                *(uint2*)&g_gvh[(size_t)gr * COUT + g4 * 4] = o;
            }
        }
    }
}

// ---------------- final smooth on [N,40], fp16 tables ----------------
__global__ void k_passCe() {
    __shared__ float red[24][44];
    int e = blockIdx.x, t = threadIdx.x;
    int beg = e * PADE;
    int cnte = g_cnt_e[e];
    int deg = min(cnte, PADE);
    if (t < 240) {
        int r = t / 10, cg = (t % 10) * 4;
        float4 acc = make_float4(0.f, 0.f, 0.f, 0.f);
        for (int i = r; i < deg; i += 24) {
            int vv = g_elist[beg + i];
            uint2 gv = *(const uint2*)&g_gvh[(size_t)vv * COUT + cg];
            float2 f0 = __half22float2(*(__half2*)&gv.x);
            float2 f1 = __half22float2(*(__half2*)&gv.y);
            acc.x += f0.x; acc.y += f0.y; acc.z += f1.x; acc.w += f1.y;
        }
        *(float4*)&red[r][cg] = acc;
    }
    __syncthreads();
    if (t < 40) {
        float s = 0.f;
        #pragma unroll
        for (int r = 0; r < 24; r++) s += red[r][t];
        g_ef2h[(size_t)e * COUT + t] = __float2half_rn(deinv_of(cnte) * s);
    }
}
__global__ void k_passCn(float* __restrict__ out) {
    __shared__ float red[24][44];
    int v = blockIdx.x, t = threadIdx.x;
    int beg = v * PADN;
    int cntv = g_cnt_v[v];
    int deg = min(cntv, PADN);
    if (t < 240) {
        int r = t / 10, cg = (t % 10) * 4;
        float4 acc = make_float4(0.f, 0.f, 0.f, 0.f);
        for (int i = r; i < deg; i += 24) {
            int e = g_nlist[beg + i];
            uint2 ev = *(const uint2*)&g_ef2h[(size_t)e * COUT + cg];
            float2 f0 = __half22float2(*(__half2*)&ev.x);
            float2 f1 = __half22float2(*(__half2*)&ev.y);
            acc.x += f0.x; acc.y += f0.y; acc.z += f1.x; acc.w += f1.y;
        }
        *(float4*)&red[r][cg] = acc;
    }
    __syncthreads();
    if (t < 40) {
        float s = 0.f;
        #pragma unroll
        for (int r = 0; r < 24; r++) s += red[r][t];
        out[(size_t)v * COUT + t] = dvis_of(cntv) * s;
    }
}

// ---------------- launch ----------------
extern "C" void kernel_launch(void* const* d_in, const int* in_sizes, int n_in,
                              void* d_out, int out_size) {
    const float* x  = (const float*)d_in[0];   // [4, NN, 256]
    const float* W1 = (const float*)d_in[1];   // [4, 256, 256]
    const float* b1 = (const float*)d_in[2];   // [4, 256] -> flat [1024]
    const float* W2 = (const float*)d_in[3];   // [1024, 40]
    const float* b2 = (const float*)d_in[4];   // [40]
    const int*   ni = (const int*)d_in[5];     // node_idx [NNZ]
    const int*   ei = (const int*)d_in[6];     // edge_idx [NNZ]
    int nnz = in_sizes[5];
    float* out = (float*)d_out;

    k_zero   <<<(NN + 255) / 256, 256>>>();
    k_fillcvt<<<FILL_BLOCKS + CVT_BLOCKS, 256>>>(ni, ei, nnz, x, W1, W2);
    k_passA  <<<NE, 128>>>();
    {
        dim3 grid((NE + 127) / 128, 2, 4);
        k_egemm<<<grid, 256>>>();       // <- 4th launch: ncu window lands here
    }
    k_passB  <<<NN, 128>>>(b1);
    k_gemm2  <<<(NN + 127) / 128, 256>>>(b2);
    k_passCe <<<NE, 256>>>();
    k_passCn <<<NN, 256>>>(out);
}

// round 14
// speedup vs baseline: 1.0195x; 1.0195x over previous
#include <cuda_runtime.h>
#include <cuda_fp16.h>
#include <mma.h>
#include <cstdint>

using namespace nvcuda;

#define NN   50000
#define NE   20000
#define NNZV 1600000
#define CH   1024   // concat(4) * hid(256)
#define CIN  256
#define COUT 40
#define PADE 192    // max edge degree slot count (Poisson(80) max ~120)
#define PADN 96     // max node degree slot count (Poisson(32) max ~58)

// cvt+zero kernel geometry (x is 4*NN*CIN = 51,200,000 halves)
#define CVT_X_T  12800000                          // x: 51.2M / 4 per-thread floats
#define CVT_W1_T (CVT_X_T + 65536)                 // W1: 262144 floats / 4
#define CVT_W2_T (CVT_W1_T + 49152)                // W2 padded: 1024*48 elems
#define CVT_BLOCKS ((CVT_W2_T + 255) / 256)        // 50448
#define ZERO_BLOCKS ((NN + 255) / 256)             // 196

// ---------------- device scratch (static; no allocations) ----------------
__device__ int   g_cnt_v[NN];
__device__ int   g_cnt_e[NE];
__device__ int   g_elist[NE * PADE];   // nodes grouped by edge (padded rows)
__device__ int   g_nlist[NN * PADN];   // edges grouped by node (padded rows)
__device__ float g_t1[NE];
__device__ __half g_xh[51200000];      // [4][NN][256] fp16 (UNSCALED)
__device__ __half g_W1h[262144];       // [4][256][256] fp16
__device__ __half g_W2h[49152];        // [1024][48] fp16 (N padded 40->48)
__device__ __half g_zh [20480000];     // [NE][CH] fp16
__device__ __half g_z2h[20480000];     // [NE][CH] fp16
__device__ __half g_hiddenh[51200000]; // [NN][CH] fp16
__device__ __half g_gvh[2000000];      // [NN][COUT] fp16 (prescaled by dv_is)
__device__ __half g_ef2h[800000];      // [NE][COUT] fp16

__device__ __forceinline__ float dvis_of(int c)  { return (c > 0) ? rsqrtf((float)c) : 0.f; }
__device__ __forceinline__ float deinv_of(int c) { return (c > 0) ? (1.f / (float)c) : 0.f; }

// ---------------- fused: fp16 conversions + count zeroing (fully independent) ----------------
__global__ void k_cvtzero(const float* __restrict__ x, const float* __restrict__ W1,
                          const float* __restrict__ W2) {
    int blk = blockIdx.x;
    if (blk < CVT_BLOCKS) {
        int tid = blk * 256 + threadIdx.x;
        if (tid < CVT_X_T) {
            int lin = tid * 4;
            float4 xv = *(const float4*)(x + lin);
            __half2 h0 = __floats2half2_rn(xv.x, xv.y);
            __half2 h1 = __floats2half2_rn(xv.z, xv.w);
            uint2 o;
            o.x = *(unsigned*)&h0;
            o.y = *(unsigned*)&h1;
            *(uint2*)&g_xh[lin] = o;
        } else if (tid < CVT_W1_T) {
            int lin = (tid - CVT_X_T) * 4;
            float4 v = *(const float4*)(W1 + lin);
            __half2 h0 = __floats2half2_rn(v.x, v.y);
            __half2 h1 = __floats2half2_rn(v.z, v.w);
            uint2 o; o.x = *(unsigned*)&h0; o.y = *(unsigned*)&h1;
            *(uint2*)&g_W1h[lin] = o;
        } else if (tid < CVT_W2_T) {
            int j2 = tid - CVT_W1_T;
            int k = j2 / 48, j = j2 % 48;
            float v = (j < COUT) ? W2[k * COUT + j] : 0.f;
            g_W2h[j2] = __float2half_rn(v);
        }
    } else {
        int i = (blk - CVT_BLOCKS) * 256 + threadIdx.x;
        if (i < NN) g_cnt_v[i] = 0;
        if (i < NE) g_cnt_e[i] = 0;
    }
}

// ---------------- one-pass CSR build: count + place via atomic slot allocation ----------------
__global__ void k_fill(const int* __restrict__ ni, const int* __restrict__ ei, int nnz) {
    int i = blockIdx.x * blockDim.x + threadIdx.x;
    if (i < nnz) {
        int v = ni[i], e = ei[i];
        int p = atomicAdd(&g_cnt_e[e], 1);
        if (p < PADE) g_elist[e * PADE + p] = v;
        int q = atomicAdd(&g_cnt_v[v], 1);
        if (q < PADN) g_nlist[v * PADN + q] = e;
    }
}

// ---------------- pass A: zh[e][:] = de_inv[e] * sum_{v in e} dvis[v]*xh[v][:]; also t1[e] ----------------
__global__ void k_passA() {
    __shared__ int   svv[128];
    __shared__ float sww[128];
    int e = blockIdx.x, t = threadIdx.x;
    int beg = e * PADE;
    int cnte = g_cnt_e[e];
    int deg = min(cnte, PADE);
    int b = t >> 5, c = (t & 31) * 8;
    const __half* xb = g_xh + (size_t)b * NN * CIN + c;
    float a0 = 0.f, a1 = 0.f, a2 = 0.f, a3 = 0.f, a4 = 0.f, a5 = 0.f, a6 = 0.f, a7 = 0.f;
    float at = 0.f;
    for (int base = 0; base < deg; base += 128) {
        int m = min(128, deg - base);
        __syncthreads();
        if (t < m) {
            int v = g_elist[beg + base + t];
            svv[t] = v;
            sww[t] = rsqrtf((float)g_cnt_v[v]);   // v in list => cnt >= 1
        }
        __syncthreads();
        #pragma unroll 8
        for (int i = 0; i < m; i++) {
            float w = sww[i];
            at += w;
            uint4 rv = *(const uint4*)(xb + (size_t)svv[i] * CIN);
            float2 f0 = __half22float2(*(__half2*)&rv.x);
            float2 f1 = __half22float2(*(__half2*)&rv.y);
            float2 f2 = __half22float2(*(__half2*)&rv.z);
            float2 f3 = __half22float2(*(__half2*)&rv.w);
            a0 = fmaf(w, f0.x, a0); a1 = fmaf(w, f0.y, a1);
            a2 = fmaf(w, f1.x, a2); a3 = fmaf(w, f1.y, a3);
            a4 = fmaf(w, f2.x, a4); a5 = fmaf(w, f2.y, a5);
            a6 = fmaf(w, f3.x, a6); a7 = fmaf(w, f3.y, a7);
        }
    }
    float sc = deinv_of(cnte);
    if (t == 0) g_t1[e] = sc * at;
    __half2 h0 = __floats2half2_rn(sc * a0, sc * a1);
    __half2 h1 = __floats2half2_rn(sc * a2, sc * a3);
    __half2 h2 = __floats2half2_rn(sc * a4, sc * a5);
    __half2 h3 = __floats2half2_rn(sc * a6, sc * a7);
    uint4 o;
    o.x = *(unsigned*)&h0; o.y = *(unsigned*)&h1;
    o.z = *(unsigned*)&h2; o.w = *(unsigned*)&h3;
    *(uint4*)&g_zh[(size_t)e * CH + t * 8] = o;
}

// ---------------- edge GEMM via wmma: z2h = zh @ blockdiag(W1h[b]) ----------------
// Tile M=128 x N=64 (acc[2][2] keeps regs low); __launch_bounds__(256,3) -> >=3 blocks/SM.
__global__ void __launch_bounds__(256, 3) k_egemm() {
    __shared__ __align__(16) union {
        struct { __half A[128][72]; __half B[64][72]; } in;   // 18432 + 9216 = 27648
        float Cf[8][32 * 36];                                  // 36864
    } sm;
    int t = threadIdx.x;
    int warp = t >> 5, lane = t & 31;
    int wm = warp >> 1, wn = warp & 1;
    int b = blockIdx.z;
    int row0 = blockIdx.x * 128;
    int col0 = blockIdx.y * 64;

    wmma::fragment<wmma::accumulator, 16, 16, 16, float> acc[2][2];
    #pragma unroll
    for (int i = 0; i < 2; i++)
        #pragma unroll
        for (int j = 0; j < 2; j++) wmma::fill_fragment(acc[i][j], 0.f);

    for (int kp = 0; kp < 256; kp += 64) {
        __syncthreads();
        #pragma unroll
        for (int i = 0; i < 4; i++) {   // A: 128x64 halfs = 1024 uint4 groups
            int g = t + 256 * i;
            int row = g >> 3, gc = (g & 7) * 8;
            int r = row0 + row;
            uint4 val = make_uint4(0u, 0u, 0u, 0u);
            if (r < NE) val = *(const uint4*)&g_zh[(size_t)r * CH + b * 256 + kp + gc];
            *(uint4*)&sm.in.A[row][gc] = val;
        }
        #pragma unroll
        for (int i = 0; i < 2; i++) {   // B: 64x64 halfs = 512 uint4 groups
            int g = t + 256 * i;
            int row = g >> 3, gc = (g & 7) * 8;
            *(uint4*)&sm.in.B[row][gc] =
                *(const uint4*)&g_W1h[b * 65536 + (kp + row) * 256 + col0 + gc];
        }
        __syncthreads();
        #pragma unroll
        for (int ks = 0; ks < 4; ks++) {
            wmma::fragment<wmma::matrix_a, 16, 16, 16, __half, wmma::row_major> af[2];
            wmma::fragment<wmma::matrix_b, 16, 16, 16, __half, wmma::row_major> bf[2];
            wmma::load_matrix_sync(af[0], &sm.in.A[wm * 32][ks * 16], 72);
            wmma::load_matrix_sync(af[1], &sm.in.A[wm * 32 + 16][ks * 16], 72);
            wmma::load_matrix_sync(bf[0], &sm.in.B[ks * 16][wn * 32], 72);
            wmma::load_matrix_sync(bf[1], &sm.in.B[ks * 16][wn * 32 + 16], 72);
            #pragma unroll
            for (int i = 0; i < 2; i++)
                #pragma unroll
                for (int j = 0; j < 2; j++)
                    wmma::mma_sync(acc[i][j], af[i], bf[j], acc[i][j]);
        }
    }
    __syncthreads();   // union reuse: all mma smem reads complete
    #pragma unroll
    for (int i = 0; i < 2; i++)
        #pragma unroll
        for (int j = 0; j < 2; j++)
            wmma::store_matrix_sync(&sm.Cf[warp][(i * 16) * 36 + j * 16], acc[i][j], 36,
                                    wmma::mem_row_major);
    __syncwarp();
    int gr = row0 + wm * 32 + lane;
    if (gr < NE) {
        size_t base = (size_t)gr * CH + b * 256 + col0 + wn * 32;
        const float* cr = &sm.Cf[warp][lane * 36];
        #pragma unroll
        for (int g4 = 0; g4 < 4; g4++) {
            float4 v0 = *(const float4*)&cr[g4 * 8];
            float4 v1 = *(const float4*)&cr[g4 * 8 + 4];
            __half2 h0 = __floats2half2_rn(v0.x, v0.y);
            __half2 h1 = __floats2half2_rn(v0.z, v0.w);
            __half2 h2 = __floats2half2_rn(v1.x, v1.y);
            __half2 h3 = __floats2half2_rn(v1.z, v1.w);
            uint4 o;
            o.x = *(unsigned*)&h0; o.y = *(unsigned*)&h1;
            o.z = *(unsigned*)&h2; o.w = *(unsigned*)&h3;
            *(uint4*)&g_z2h[base + g4 * 8] = o;
        }
    }
}

// ---------------- pass B: hiddenh[v][:] = relu(dv_is[v]*sum z2h + s[v]*b1[:]); s inline ----------------
__global__ void k_passB(const float* __restrict__ b1) {
    __shared__ int   see[128];
    __shared__ float st1[128];
    int v = blockIdx.x, t = threadIdx.x;
    int beg = v * PADN;
    int cntv = g_cnt_v[v];
    int deg = min(cntv, PADN);
    const __half* zb = g_z2h + t * 8;
    float a0 = 0.f, a1 = 0.f, a2 = 0.f, a3 = 0.f, a4 = 0.f, a5 = 0.f, a6 = 0.f, a7 = 0.f;
    float at = 0.f;
    for (int base = 0; base < deg; base += 128) {
        int m = min(128, deg - base);
        __syncthreads();
        if (t < m) {
            int ee = g_nlist[beg + base + t];
            see[t] = ee;
            st1[t] = g_t1[ee];
        }
        __syncthreads();
        #pragma unroll 8
        for (int i = 0; i < m; i++) {
            at += st1[i];
            uint4 rv = *(const uint4*)(zb + (size_t)see[i] * CH);
            float2 f0 = __half22float2(*(__half2*)&rv.x);
            float2 f1 = __half22float2(*(__half2*)&rv.y);
            float2 f2 = __half22float2(*(__half2*)&rv.z);
            float2 f3 = __half22float2(*(__half2*)&rv.w);
            a0 += f0.x; a1 += f0.y; a2 += f1.x; a3 += f1.y;
            a4 += f2.x; a5 += f2.y; a6 += f3.x; a7 += f3.y;
        }
    }
    float w = dvis_of(cntv);
    float sv = w * at;   // s[v] = dvis[v] * sum t1
    int c = t * 8;
    float4 bb0 = *(const float4*)&b1[c];
    float4 bb1 = *(const float4*)&b1[c + 4];
    float r0 = fmaxf(w * a0 + sv * bb0.x, 0.f);
    float r1 = fmaxf(w * a1 + sv * bb0.y, 0.f);
    float r2 = fmaxf(w * a2 + sv * bb0.z, 0.f);
    float r3 = fmaxf(w * a3 + sv * bb0.w, 0.f);
    float r4 = fmaxf(w * a4 + sv * bb1.x, 0.f);
    float r5 = fmaxf(w * a5 + sv * bb1.y, 0.f);
    float r6 = fmaxf(w * a6 + sv * bb1.z, 0.f);
    float r7 = fmaxf(w * a7 + sv * bb1.w, 0.f);
    __half2 h0 = __floats2half2_rn(r0, r1);
    __half2 h1 = __floats2half2_rn(r2, r3);
    __half2 h2 = __floats2half2_rn(r4, r5);
    __half2 h3 = __floats2half2_rn(r6, r7);
    uint4 o;
    o.x = *(unsigned*)&h0; o.y = *(unsigned*)&h1;
    o.z = *(unsigned*)&h2; o.w = *(unsigned*)&h3;
    *(uint4*)&g_hiddenh[(size_t)v * CH + c] = o;
}

// ---------------- GEMM2 via wmma: gvh = fp16(dvis * (hiddenh @ W2h + b2)) ----------------
__global__ void k_gemm2(const float* __restrict__ b2) {
    __shared__ __align__(16) union {
        struct { __half A[128][72]; __half B[64][56]; } in;   // 18432 + 7168
        float C[8][832];                                       // 26624
    } sm;
    int t = threadIdx.x;
    int warp = t >> 5, lane = t & 31;
    int row0 = blockIdx.x * 128;

    wmma::fragment<wmma::accumulator, 16, 16, 16, float> acc[3];
    #pragma unroll
    for (int j = 0; j < 3; j++) wmma::fill_fragment(acc[j], 0.f);

    for (int kp = 0; kp < CH; kp += 64) {
        __syncthreads();
        #pragma unroll
        for (int i = 0; i < 4; i++) {   // A: 128x64
            int g = t + 256 * i;
            int row = g >> 3, gc = (g & 7) * 8;
            int r = row0 + row;
            uint4 val = make_uint4(0u, 0u, 0u, 0u);
            if (r < NN) val = *(const uint4*)&g_hiddenh[(size_t)r * CH + kp + gc];
            *(uint4*)&sm.in.A[row][gc] = val;
        }
        #pragma unroll
        for (int i = 0; i < 2; i++) {   // B: 64x48 halfs = 384 uint4 groups
            int g = t + 256 * i;
            if (g < 384) {
                int row = g / 6, gc = (g % 6) * 8;
                *(uint4*)&sm.in.B[row][gc] = *(const uint4*)&g_W2h[(kp + row) * 48 + gc];
            }
        }
        __syncthreads();
        #pragma unroll
        for (int ks = 0; ks < 4; ks++) {
            wmma::fragment<wmma::matrix_a, 16, 16, 16, __half, wmma::row_major> af;
            wmma::load_matrix_sync(af, &sm.in.A[warp * 16][ks * 16], 72);
            #pragma unroll
            for (int j = 0; j < 3; j++) {
                wmma::fragment<wmma::matrix_b, 16, 16, 16, __half, wmma::row_major> bf;
                wmma::load_matrix_sync(bf, &sm.in.B[ks * 16][j * 16], 56);
                wmma::mma_sync(acc[j], af, bf, acc[j]);
            }
        }
    }
    __syncthreads();
    #pragma unroll
    for (int j = 0; j < 3; j++)
        wmma::store_matrix_sync(&sm.C[warp][j * 16], acc[j], 52, wmma::mem_row_major);
    __syncwarp();
    if (lane < 16) {
        int gr = row0 + warp * 16 + lane;
        if (gr < NN) {
            float w = dvis_of(g_cnt_v[gr]);
            const float* cr = &sm.C[warp][lane * 52];
            #pragma unroll
            for (int g4 = 0; g4 < 10; g4++) {
                float4 c0 = *(const float4*)&cr[g4 * 4];
                float4 d0 = *(const float4*)&b2[g4 * 4];
                __half2 h0 = __floats2half2_rn(w * (c0.x + d0.x), w * (c0.y + d0.y));
                __half2 h1 = __floats2half2_rn(w * (c0.z + d0.z), w * (c0.w + d0.w));
                uint2 o;
                o.x = *(unsigned*)&h0; o.y = *(unsigned*)&h1;
                *(uint2*)&g_gvh[(size_t)gr * COUT + g4 * 4] = o;
            }
        }
    }
}

// ---------------- final smooth on [N,40], fp16 tables ----------------
__global__ void k_passCe() {
    __shared__ float red[24][44];
    int e = blockIdx.x, t = threadIdx.x;
    int beg = e * PADE;
    int cnte = g_cnt_e[e];
    int deg = min(cnte, PADE);
    if (t < 240) {
        int r = t / 10, cg = (t % 10) * 4;
        float4 acc = make_float4(0.f, 0.f, 0.f, 0.f);
        for (int i = r; i < deg; i += 24) {
            int vv = g_elist[beg + i];
            uint2 gv = *(const uint2*)&g_gvh[(size_t)vv * COUT + cg];
            float2 f0 = __half22float2(*(__half2*)&gv.x);
            float2 f1 = __half22float2(*(__half2*)&gv.y);
            acc.x += f0.x; acc.y += f0.y; acc.z += f1.x; acc.w += f1.y;
        }
        *(float4*)&red[r][cg] = acc;
    }
    __syncthreads();
    if (t < 40) {
        float s = 0.f;
        #pragma unroll
        for (int r = 0; r < 24; r++) s += red[r][t];
        g_ef2h[(size_t)e * COUT + t] = __float2half_rn(deinv_of(cnte) * s);
    }
}
__global__ void k_passCn(float* __restrict__ out) {
    __shared__ float red[24][44];
    int v = blockIdx.x, t = threadIdx.x;
    int beg = v * PADN;
    int cntv = g_cnt_v[v];
    int deg = min(cntv, PADN);
    if (t < 240) {
        int r = t / 10, cg = (t % 10) * 4;
        float4 acc = make_float4(0.f, 0.f, 0.f, 0.f);
        for (int i = r; i < deg; i += 24) {
            int e = g_nlist[beg + i];
            uint2 ev = *(const uint2*)&g_ef2h[(size_t)e * COUT + cg];
            float2 f0 = __half22float2(*(__half2*)&ev.x);
            float2 f1 = __half22float2(*(__half2*)&ev.y);
            acc.x += f0.x; acc.y += f0.y; acc.z += f1.x; acc.w += f1.y;
        }
        *(float4*)&red[r][cg] = acc;
    }
    __syncthreads();
    if (t < 40) {
        float s = 0.f;
        #pragma unroll
        for (int r = 0; r < 24; r++) s += red[r][t];
        out[(size_t)v * COUT + t] = dvis_of(cntv) * s;
    }
}

// ---------------- launch ----------------
extern "C" void kernel_launch(void* const* d_in, const int* in_sizes, int n_in,
                              void* d_out, int out_size) {
    const float* x  = (const float*)d_in[0];   // [4, NN, 256]
    const float* W1 = (const float*)d_in[1];   // [4, 256, 256]
    const float* b1 = (const float*)d_in[2];   // [4, 256] -> flat [1024]
    const float* W2 = (const float*)d_in[3];   // [1024, 40]
    const float* b2 = (const float*)d_in[4];   // [40]
    const int*   ni = (const int*)d_in[5];     // node_idx [NNZ]
    const int*   ei = (const int*)d_in[6];     // edge_idx [NNZ]
    int nnz = in_sizes[5];
    float* out = (float*)d_out;

    k_cvtzero<<<CVT_BLOCKS + ZERO_BLOCKS, 256>>>(x, W1, W2);   // (1) cvt + zero counts
    k_fill   <<<(nnz + 255) / 256, 256>>>(ni, ei, nnz);        // (2)
    k_passA  <<<NE, 128>>>();                                  // (3)
    {
        dim3 grid((NE + 127) / 128, 4, 4);
        k_egemm<<<grid, 256>>>();                              // (4) <- ncu window
    }
    k_passB  <<<NN, 128>>>(b1);
    k_gemm2  <<<(NN + 127) / 128, 256>>>(b2);
    k_passCe <<<NE, 256>>>();
    k_passCn <<<NN, 256>>>(out);
}

// round 15
// speedup vs baseline: 1.0288x; 1.0091x over previous
#include <cuda_runtime.h>
#include <cuda_fp16.h>
#include <mma.h>
#include <cstdint>

using namespace nvcuda;

#define NN   50000
#define NE   20000
#define NNZV 1600000
#define CH   1024   // concat(4) * hid(256)
#define CIN  256
#define COUT 40
#define PADE 192    // max edge degree slot count (Poisson(80) max ~120)
#define PADN 96     // max node degree slot count (Poisson(32) max ~58)

// cvt kernel geometry (x is 4*NN*CIN = 51,200,000 halves)
#define CVT_X_T  12800000                          // x: 51.2M / 4 per-thread floats
#define CVT_W1_T (CVT_X_T + 65536)                 // W1: 262144 floats / 4
#define CVT_W2_T (CVT_W1_T + 49152)                // W2 padded: 1024*48 elems

// ---------------- device scratch (static; no allocations) ----------------
__device__ int   g_cnt_v[NN];
__device__ int   g_cnt_e[NE];
__device__ int   g_elist[NE * PADE];   // nodes grouped by edge (padded rows)
__device__ int   g_nlist[NN * PADN];   // edges grouped by node (padded rows)
__device__ float g_t1[NE];
__device__ __half g_xh[51200000];      // [4][NN][256] fp16 (UNSCALED)
__device__ __half g_W1h[262144];       // [4][256][256] fp16
__device__ __half g_W2h[49152];        // [1024][48] fp16 (N padded 40->48)
__device__ __half g_zh [20480000];     // [NE][CH] fp16
__device__ __half g_z2h[20480000];     // [NE][CH] fp16
__device__ __half g_hiddenh[51200000]; // [NN][CH] fp16
__device__ __half g_gvh[2000000];      // [NN][COUT] fp16 (prescaled by dv_is)
__device__ __half g_ef2h[800000];      // [NE][COUT] fp16

__device__ __forceinline__ float dvis_of(int c)  { return (c > 0) ? rsqrtf((float)c) : 0.f; }
__device__ __forceinline__ float deinv_of(int c) { return (c > 0) ? (1.f / (float)c) : 0.f; }

// ---------------- init ----------------
__global__ void k_zero() {
    int i = blockIdx.x * blockDim.x + threadIdx.x;
    if (i < NN) g_cnt_v[i] = 0;
    if (i < NE) g_cnt_e[i] = 0;
}

// ---------------- one-pass CSR build: count + place via atomic slot allocation ----------------
// Runs on a CLEAN L2 (before the big streaming conversion) - atomics don't fight writeback.
__global__ void k_fill(const int* __restrict__ ni, const int* __restrict__ ei, int nnz) {
    int i = blockIdx.x * blockDim.x + threadIdx.x;
    if (i < nnz) {
        int v = ni[i], e = ei[i];
        int p = atomicAdd(&g_cnt_e[e], 1);
        if (p < PADE) g_elist[e * PADE + p] = v;
        int q = atomicAdd(&g_cnt_v[v], 1);
        if (q < PADN) g_nlist[v * PADN + q] = e;
    }
}

// ---------------- fp16 conversions (x unscaled; runs right before passA so xh is L2-warm) ----------------
__global__ void k_cvt(const float* __restrict__ x, const float* __restrict__ W1,
                      const float* __restrict__ W2) {
    int tid = blockIdx.x * blockDim.x + threadIdx.x;
    if (tid < CVT_X_T) {
        int lin = tid * 4;
        float4 xv = *(const float4*)(x + lin);
        __half2 h0 = __floats2half2_rn(xv.x, xv.y);
        __half2 h1 = __floats2half2_rn(xv.z, xv.w);
        uint2 o;
        o.x = *(unsigned*)&h0;
        o.y = *(unsigned*)&h1;
        *(uint2*)&g_xh[lin] = o;
    } else if (tid < CVT_W1_T) {
        int lin = (tid - CVT_X_T) * 4;
        float4 v = *(const float4*)(W1 + lin);
        __half2 h0 = __floats2half2_rn(v.x, v.y);
        __half2 h1 = __floats2half2_rn(v.z, v.w);
        uint2 o; o.x = *(unsigned*)&h0; o.y = *(unsigned*)&h1;
        *(uint2*)&g_W1h[lin] = o;
    } else if (tid < CVT_W2_T) {
        int j2 = tid - CVT_W1_T;
        int k = j2 / 48, j = j2 % 48;
        float v = (j < COUT) ? W2[k * COUT + j] : 0.f;
        g_W2h[j2] = __float2half_rn(v);
    }
}

// ---------------- pass A: zh[e][:] = de_inv[e] * sum_{v in e} dvis[v]*xh[v][:]; also t1[e] ----------------
__global__ void k_passA() {
    __shared__ int   svv[128];
    __shared__ float sww[128];
    int e = blockIdx.x, t = threadIdx.x;
    int beg = e * PADE;
    int cnte = g_cnt_e[e];
    int deg = min(cnte, PADE);
    int b = t >> 5, c = (t & 31) * 8;
    const __half* xb = g_xh + (size_t)b * NN * CIN + c;
    float a0 = 0.f, a1 = 0.f, a2 = 0.f, a3 = 0.f, a4 = 0.f, a5 = 0.f, a6 = 0.f, a7 = 0.f;
    float at = 0.f;
    for (int base = 0; base < deg; base += 128) {
        int m = min(128, deg - base);
        __syncthreads();
        if (t < m) {
            int v = g_elist[beg + base + t];
            svv[t] = v;
            sww[t] = rsqrtf((float)g_cnt_v[v]);   // v in list => cnt >= 1
        }
        __syncthreads();
        #pragma unroll 8
        for (int i = 0; i < m; i++) {
            float w = sww[i];
            at += w;
            uint4 rv = *(const uint4*)(xb + (size_t)svv[i] * CIN);
            float2 f0 = __half22float2(*(__half2*)&rv.x);
            float2 f1 = __half22float2(*(__half2*)&rv.y);
            float2 f2 = __half22float2(*(__half2*)&rv.z);
            float2 f3 = __half22float2(*(__half2*)&rv.w);
            a0 = fmaf(w, f0.x, a0); a1 = fmaf(w, f0.y, a1);
            a2 = fmaf(w, f1.x, a2); a3 = fmaf(w, f1.y, a3);
            a4 = fmaf(w, f2.x, a4); a5 = fmaf(w, f2.y, a5);
            a6 = fmaf(w, f3.x, a6); a7 = fmaf(w, f3.y, a7);
        }
    }
    float sc = deinv_of(cnte);
    if (t == 0) g_t1[e] = sc * at;
    __half2 h0 = __floats2half2_rn(sc * a0, sc * a1);
    __half2 h1 = __floats2half2_rn(sc * a2, sc * a3);
    __half2 h2 = __floats2half2_rn(sc * a4, sc * a5);
    __half2 h3 = __floats2half2_rn(sc * a6, sc * a7);
    uint4 o;
    o.x = *(unsigned*)&h0; o.y = *(unsigned*)&h1;
    o.z = *(unsigned*)&h2; o.w = *(unsigned*)&h3;
    *(uint4*)&g_zh[(size_t)e * CH + t * 8] = o;
}

// ---------------- edge GEMM via wmma: z2h = zh @ blockdiag(W1h[b]) ----------------
// Tile M=128 x N=64 (acc[2][2] keeps regs low); __launch_bounds__(256,3) -> 3 blocks/SM (verified occ 34.5%).
__global__ void __launch_bounds__(256, 3) k_egemm() {
    __shared__ __align__(16) union {
        struct { __half A[128][72]; __half B[64][72]; } in;   // 18432 + 9216 = 27648
        float Cf[8][32 * 36];                                  // 36864
    } sm;
    int t = threadIdx.x;
    int warp = t >> 5, lane = t & 31;
    int wm = warp >> 1, wn = warp & 1;
    int b = blockIdx.z;
    int row0 = blockIdx.x * 128;
    int col0 = blockIdx.y * 64;

    wmma::fragment<wmma::accumulator, 16, 16, 16, float> acc[2][2];
    #pragma unroll
    for (int i = 0; i < 2; i++)
        #pragma unroll
        for (int j = 0; j < 2; j++) wmma::fill_fragment(acc[i][j], 0.f);

    for (int kp = 0; kp < 256; kp += 64) {
        __syncthreads();
        #pragma unroll
        for (int i = 0; i < 4; i++) {   // A: 128x64 halfs = 1024 uint4 groups
            int g = t + 256 * i;
            int row = g >> 3, gc = (g & 7) * 8;
            int r = row0 + row;
            uint4 val = make_uint4(0u, 0u, 0u, 0u);
            if (r < NE) val = *(const uint4*)&g_zh[(size_t)r * CH + b * 256 + kp + gc];
            *(uint4*)&sm.in.A[row][gc] = val;
        }
        #pragma unroll
        for (int i = 0; i < 2; i++) {   // B: 64x64 halfs = 512 uint4 groups
            int g = t + 256 * i;
            int row = g >> 3, gc = (g & 7) * 8;
            *(uint4*)&sm.in.B[row][gc] =
                *(const uint4*)&g_W1h[b * 65536 + (kp + row) * 256 + col0 + gc];
        }
        __syncthreads();
        #pragma unroll
        for (int ks = 0; ks < 4; ks++) {
            wmma::fragment<wmma::matrix_a, 16, 16, 16, __half, wmma::row_major> af[2];
            wmma::fragment<wmma::matrix_b, 16, 16, 16, __half, wmma::row_major> bf[2];
            wmma::load_matrix_sync(af[0], &sm.in.A[wm * 32][ks * 16], 72);
            wmma::load_matrix_sync(af[1], &sm.in.A[wm * 32 + 16][ks * 16], 72);
            wmma::load_matrix_sync(bf[0], &sm.in.B[ks * 16][wn * 32], 72);
            wmma::load_matrix_sync(bf[1], &sm.in.B[ks * 16][wn * 32 + 16], 72);
            #pragma unroll
            for (int i = 0; i < 2; i++)
                #pragma unroll
                for (int j = 0; j < 2; j++)
                    wmma::mma_sync(acc[i][j], af[i], bf[j], acc[i][j]);
        }
    }
    __syncthreads();   // union reuse: all mma smem reads complete
    #pragma unroll
    for (int i = 0; i < 2; i++)
        #pragma unroll
        for (int j = 0; j < 2; j++)
            wmma::store_matrix_sync(&sm.Cf[warp][(i * 16) * 36 + j * 16], acc[i][j], 36,
                                    wmma::mem_row_major);
    __syncwarp();
    int gr = row0 + wm * 32 + lane;
    if (gr < NE) {
        size_t base = (size_t)gr * CH + b * 256 + col0 + wn * 32;
        const float* cr = &sm.Cf[warp][lane * 36];
        #pragma unroll
        for (int g4 = 0; g4 < 4; g4++) {
            float4 v0 = *(const float4*)&cr[g4 * 8];
            float4 v1 = *(const float4*)&cr[g4 * 8 + 4];
            __half2 h0 = __floats2half2_rn(v0.x, v0.y);
            __half2 h1 = __floats2half2_rn(v0.z, v0.w);
            __half2 h2 = __floats2half2_rn(v1.x, v1.y);
            __half2 h3 = __floats2half2_rn(v1.z, v1.w);
            uint4 o;
            o.x = *(unsigned*)&h0; o.y = *(unsigned*)&h1;
            o.z = *(unsigned*)&h2; o.w = *(unsigned*)&h3;
            *(uint4*)&g_z2h[base + g4 * 8] = o;
        }
    }
}

// ---------------- pass B: hiddenh[v][:] = relu(dv_is[v]*sum z2h + s[v]*b1[:]); s inline ----------------
__global__ void k_passB(const float* __restrict__ b1) {
    __shared__ int   see[128];
    __shared__ float st1[128];
    int v = blockIdx.x, t = threadIdx.x;
    int beg = v * PADN;
    int cntv = g_cnt_v[v];
    int deg = min(cntv, PADN);
    const __half* zb = g_z2h + t * 8;
    float a0 = 0.f, a1 = 0.f, a2 = 0.f, a3 = 0.f, a4 = 0.f, a5 = 0.f, a6 = 0.f, a7 = 0.f;
    float at = 0.f;
    for (int base = 0; base < deg; base += 128) {
        int m = min(128, deg - base);
        __syncthreads();
        if (t < m) {
            int ee = g_nlist[beg + base + t];
            see[t] = ee;
            st1[t] = g_t1[ee];
        }
        __syncthreads();
        #pragma unroll 8
        for (int i = 0; i < m; i++) {
            at += st1[i];
            uint4 rv = *(const uint4*)(zb + (size_t)see[i] * CH);
            float2 f0 = __half22float2(*(__half2*)&rv.x);
            float2 f1 = __half22float2(*(__half2*)&rv.y);
            float2 f2 = __half22float2(*(__half2*)&rv.z);
            float2 f3 = __half22float2(*(__half2*)&rv.w);
            a0 += f0.x; a1 += f0.y; a2 += f1.x; a3 += f1.y;
            a4 += f2.x; a5 += f2.y; a6 += f3.x; a7 += f3.y;
        }
    }
    float w = dvis_of(cntv);
    float sv = w * at;   // s[v] = dvis[v] * sum t1
    int c = t * 8;
    float4 bb0 = *(const float4*)&b1[c];
    float4 bb1 = *(const float4*)&b1[c + 4];
    float r0 = fmaxf(w * a0 + sv * bb0.x, 0.f);
    float r1 = fmaxf(w * a1 + sv * bb0.y, 0.f);
    float r2 = fmaxf(w * a2 + sv * bb0.z, 0.f);
    float r3 = fmaxf(w * a3 + sv * bb0.w, 0.f);
    float r4 = fmaxf(w * a4 + sv * bb1.x, 0.f);
    float r5 = fmaxf(w * a5 + sv * bb1.y, 0.f);
    float r6 = fmaxf(w * a6 + sv * bb1.z, 0.f);
    float r7 = fmaxf(w * a7 + sv * bb1.w, 0.f);
    __half2 h0 = __floats2half2_rn(r0, r1);
    __half2 h1 = __floats2half2_rn(r2, r3);
    __half2 h2 = __floats2half2_rn(r4, r5);
    __half2 h3 = __floats2half2_rn(r6, r7);
    uint4 o;
    o.x = *(unsigned*)&h0; o.y = *(unsigned*)&h1;
    o.z = *(unsigned*)&h2; o.w = *(unsigned*)&h3;
    *(uint4*)&g_hiddenh[(size_t)v * CH + c] = o;
}

// ---------------- GEMM2 via wmma: gvh = fp16(dvis * (hiddenh @ W2h + b2)) ----------------
__global__ void k_gemm2(const float* __restrict__ b2) {
    __shared__ __align__(16) union {
        struct { __half A[128][72]; __half B[64][56]; } in;   // 18432 + 7168
        float C[8][832];                                       // 26624
    } sm;
    int t = threadIdx.x;
    int warp = t >> 5, lane = t & 31;
    int row0 = blockIdx.x * 128;

    wmma::fragment<wmma::accumulator, 16, 16, 16, float> acc[3];
    #pragma unroll
    for (int j = 0; j < 3; j++) wmma::fill_fragment(acc[j], 0.f);

    for (int kp = 0; kp < CH; kp += 64) {
        __syncthreads();
        #pragma unroll
        for (int i = 0; i < 4; i++) {   // A: 128x64
            int g = t + 256 * i;
            int row = g >> 3, gc = (g & 7) * 8;
            int r = row0 + row;
            uint4 val = make_uint4(0u, 0u, 0u, 0u);
            if (r < NN) val = *(const uint4*)&g_hiddenh[(size_t)r * CH + kp + gc];
            *(uint4*)&sm.in.A[row][gc] = val;
        }
        #pragma unroll
        for (int i = 0; i < 2; i++) {   // B: 64x48 halfs = 384 uint4 groups
            int g = t + 256 * i;
            if (g < 384) {
                int row = g / 6, gc = (g % 6) * 8;
                *(uint4*)&sm.in.B[row][gc] = *(const uint4*)&g_W2h[(kp + row) * 48 + gc];
            }
        }
        __syncthreads();
        #pragma unroll
        for (int ks = 0; ks < 4; ks++) {
            wmma::fragment<wmma::matrix_a, 16, 16, 16, __half, wmma::row_major> af;
            wmma::load_matrix_sync(af, &sm.in.A[warp * 16][ks * 16], 72);
            #pragma unroll
            for (int j = 0; j < 3; j++) {
                wmma::fragment<wmma::matrix_b, 16, 16, 16, __half, wmma::row_major> bf;
                wmma::load_matrix_sync(bf, &sm.in.B[ks * 16][j * 16], 56);
                wmma::mma_sync(acc[j], af, bf, acc[j]);
            }
        }
    }
    __syncthreads();
    #pragma unroll
    for (int j = 0; j < 3; j++)
        wmma::store_matrix_sync(&sm.C[warp][j * 16], acc[j], 52, wmma::mem_row_major);
    __syncwarp();
    if (lane < 16) {
        int gr = row0 + warp * 16 + lane;
        if (gr < NN) {
            float w = dvis_of(g_cnt_v[gr]);
            const float* cr = &sm.C[warp][lane * 52];
            #pragma unroll
            for (int g4 = 0; g4 < 10; g4++) {
                float4 c0 = *(const float4*)&cr[g4 * 4];
                float4 d0 = *(const float4*)&b2[g4 * 4];
                __half2 h0 = __floats2half2_rn(w * (c0.x + d0.x), w * (c0.y + d0.y));
                __half2 h1 = __floats2half2_rn(w * (c0.z + d0.z), w * (c0.w + d0.w));
                uint2 o;
                o.x = *(unsigned*)&h0; o.y = *(unsigned*)&h1;
                *(uint2*)&g_gvh[(size_t)gr * COUT + g4 * 4] = o;
            }
        }
    }
}

// ---------------- final smooth on [N,40], fp16 tables ----------------
__global__ void k_passCe() {
    __shared__ float red[24][44];
    int e = blockIdx.x, t = threadIdx.x;
    int beg = e * PADE;
    int cnte = g_cnt_e[e];
    int deg = min(cnte, PADE);
    if (t < 240) {
        int r = t / 10, cg = (t % 10) * 4;
        float4 acc = make_float4(0.f, 0.f, 0.f, 0.f);
        for (int i = r; i < deg; i += 24) {
            int vv = g_elist[beg + i];
            uint2 gv = *(const uint2*)&g_gvh[(size_t)vv * COUT + cg];
            float2 f0 = __half22float2(*(__half2*)&gv.x);
            float2 f1 = __half22float2(*(__half2*)&gv.y);
            acc.x += f0.x; acc.y += f0.y; acc.z += f1.x; acc.w += f1.y;
        }
        *(float4*)&red[r][cg] = acc;
    }
    __syncthreads();
    if (t < 40) {
        float s = 0.f;
        #pragma unroll
        for (int r = 0; r < 24; r++) s += red[r][t];
        g_ef2h[(size_t)e * COUT + t] = __float2half_rn(deinv_of(cnte) * s);
    }
}
__global__ void k_passCn(float* __restrict__ out) {
    __shared__ float red[24][44];
    int v = blockIdx.x, t = threadIdx.x;
    int beg = v * PADN;
    int cntv = g_cnt_v[v];
    int deg = min(cntv, PADN);
    if (t < 240) {
        int r = t / 10, cg = (t % 10) * 4;
        float4 acc = make_float4(0.f, 0.f, 0.f, 0.f);
        for (int i = r; i < deg; i += 24) {
            int e = g_nlist[beg + i];
            uint2 ev = *(const uint2*)&g_ef2h[(size_t)e * COUT + cg];
            float2 f0 = __half22float2(*(__half2*)&ev.x);
            float2 f1 = __half22float2(*(__half2*)&ev.y);
            acc.x += f0.x; acc.y += f0.y; acc.z += f1.x; acc.w += f1.y;
        }
        *(float4*)&red[r][cg] = acc;
    }
    __syncthreads();
    if (t < 40) {
        float s = 0.f;
        #pragma unroll
        for (int r = 0; r < 24; r++) s += red[r][t];
        out[(size_t)v * COUT + t] = dvis_of(cntv) * s;
    }
}

// ---------------- launch ----------------
extern "C" void kernel_launch(void* const* d_in, const int* in_sizes, int n_in,
                              void* d_out, int out_size) {
    const float* x  = (const float*)d_in[0];   // [4, NN, 256]
    const float* W1 = (const float*)d_in[1];   // [4, 256, 256]
    const float* b1 = (const float*)d_in[2];   // [4, 256] -> flat [1024]
    const float* W2 = (const float*)d_in[3];   // [1024, 40]
    const float* b2 = (const float*)d_in[4];   // [40]
    const int*   ni = (const int*)d_in[5];     // node_idx [NNZ]
    const int*   ei = (const int*)d_in[6];     // edge_idx [NNZ]
    int nnz = in_sizes[5];
    float* out = (float*)d_out;

    k_zero  <<<(NN + 255) / 256, 256>>>();                    // (1) tiny
    k_fill  <<<(nnz + 255) / 256, 256>>>(ni, ei, nnz);        // (2) atomics on clean L2
    k_cvt   <<<(CVT_W2_T + 255) / 256, 256>>>(x, W1, W2);     // (3) streaming; leaves xh warm
    k_passA <<<NE, 128>>>();                                  // (4) <- ncu window
    {
        dim3 grid((NE + 127) / 128, 4, 4);
        k_egemm<<<grid, 256>>>();
    }
    k_passB <<<NN, 128>>>(b1);
    k_gemm2 <<<(NN + 127) / 128, 256>>>(b2);
    k_passCe<<<NE, 256>>>();
    k_passCn<<<NN, 256>>>(out);
}

// round 16
// speedup vs baseline: 1.0686x; 1.0388x over previous
#include <cuda_runtime.h>
#include <cuda_fp16.h>
#include <mma.h>
#include <cstdint>

using namespace nvcuda;

#define NN   50000
#define NE   20000
#define NNZV 1600000
#define CH   1024   // concat(4) * hid(256)
#define CIN  256
#define COUT 40
#define PADE 192    // max edge degree slot count (Poisson(80) max ~120)
#define PADN 96     // max node degree slot count (Poisson(32) max ~58)

// cvt kernel geometry (x is 4*NN*CIN = 51,200,000 halves)
#define CVT_X_T  12800000                          // x: 51.2M / 4 per-thread floats
#define CVT_W1_T (CVT_X_T + 65536)                 // W1: 262144 floats / 4
#define CVT_W2_T (CVT_W1_T + 49152)                // W2 padded: 1024*48 elems

// ---------------- device scratch (static; no allocations) ----------------
__device__ int   g_cnt_v[NN];
__device__ int   g_cnt_e[NE];
__device__ int   g_elist[NE * PADE];   // nodes grouped by edge (padded rows)
__device__ int   g_nlist[NN * PADN];   // edges grouped by node (padded rows)
__device__ float g_t1[NE];
__device__ __half g_xh[51200000];      // [4][NN][256] fp16, PRESCALED by dv_is
__device__ __half g_W1h[262144];       // [4][256][256] fp16
__device__ __half g_W2h[49152];        // [1024][48] fp16 (N padded 40->48)
__device__ __half g_zh [20480000];     // [NE][CH] fp16
__device__ __half g_z2h[20480000];     // [NE][CH] fp16
__device__ __half g_hiddenh[51200000]; // [NN][CH] fp16
__device__ __half g_gvh[2000000];      // [NN][COUT] fp16 (prescaled by dv_is)
__device__ __half g_ef2h[800000];      // [NE][COUT] fp16

__device__ __forceinline__ float dvis_of(int c)  { return (c > 0) ? rsqrtf((float)c) : 0.f; }
__device__ __forceinline__ float deinv_of(int c) { return (c > 0) ? (1.f / (float)c) : 0.f; }

// ---------------- init ----------------
__global__ void k_zero() {
    int i = blockIdx.x * blockDim.x + threadIdx.x;
    if (i < NN) g_cnt_v[i] = 0;
    if (i < NE) g_cnt_e[i] = 0;
}

// ---------------- one-pass CSR build: count + place via atomic slot allocation ----------------
// Runs on a CLEAN L2 (before the big streaming conversion).
__global__ void k_fill(const int* __restrict__ ni, const int* __restrict__ ei, int nnz) {
    int i = blockIdx.x * blockDim.x + threadIdx.x;
    if (i < nnz) {
        int v = ni[i], e = ei[i];
        int p = atomicAdd(&g_cnt_e[e], 1);
        if (p < PADE) g_elist[e * PADE + p] = v;
        int q = atomicAdd(&g_cnt_v[v], 1);
        if (q < PADN) g_nlist[v * PADN + q] = e;
    }
}

// ---------------- fp16 conversions; x PRESCALED by dv_is (counts available: fill ran first) ----------------
__global__ void k_cvt(const float* __restrict__ x, const float* __restrict__ W1,
                      const float* __restrict__ W2) {
    int tid = blockIdx.x * blockDim.x + threadIdx.x;
    if (tid < CVT_X_T) {
        int lin = tid * 4;
        int row = lin >> 8;          // index in [0, 4*NN)
        int node = row % NN;
        float w = dvis_of(g_cnt_v[node]);
        float4 xv = *(const float4*)(x + lin);
        __half2 h0 = __floats2half2_rn(w * xv.x, w * xv.y);
        __half2 h1 = __floats2half2_rn(w * xv.z, w * xv.w);
        uint2 o;
        o.x = *(unsigned*)&h0;
        o.y = *(unsigned*)&h1;
        *(uint2*)&g_xh[lin] = o;
    } else if (tid < CVT_W1_T) {
        int lin = (tid - CVT_X_T) * 4;
        float4 v = *(const float4*)(W1 + lin);
        __half2 h0 = __floats2half2_rn(v.x, v.y);
        __half2 h1 = __floats2half2_rn(v.z, v.w);
        uint2 o; o.x = *(unsigned*)&h0; o.y = *(unsigned*)&h1;
        *(uint2*)&g_W1h[lin] = o;
    } else if (tid < CVT_W2_T) {
        int j2 = tid - CVT_W1_T;
        int k = j2 / 48, j = j2 % 48;
        float v = (j < COUT) ? W2[k * COUT + j] : 0.f;
        g_W2h[j2] = __float2half_rn(v);
    }
}

// ---------------- pass A: zh[e][:] = de_inv[e] * sum_{v in e} xh[v][:] (xh prescaled); also t1[e] ----------------
// r12-proven shape: plain FADD accumulation, 32 regs, occ ~92%.
__global__ void __launch_bounds__(128, 16) k_passA() {
    __shared__ int   svv[128];
    __shared__ float sww[128];
    int e = blockIdx.x, t = threadIdx.x;
    int beg = e * PADE;
    int cnte = g_cnt_e[e];
    int deg = min(cnte, PADE);
    int b = t >> 5, c = (t & 31) * 8;
    const __half* xb = g_xh + (size_t)b * NN * CIN + c;
    float a0 = 0.f, a1 = 0.f, a2 = 0.f, a3 = 0.f, a4 = 0.f, a5 = 0.f, a6 = 0.f, a7 = 0.f;
    float at = 0.f;
    for (int base = 0; base < deg; base += 128) {
        int m = min(128, deg - base);
        __syncthreads();
        if (t < m) {
            int v = g_elist[beg + base + t];
            svv[t] = v;
            sww[t] = rsqrtf((float)g_cnt_v[v]);   // v in list => cnt >= 1
        }
        __syncthreads();
        #pragma unroll 8
        for (int i = 0; i < m; i++) {
            at += sww[i];
            uint4 rv = *(const uint4*)(xb + (size_t)svv[i] * CIN);
            float2 f0 = __half22float2(*(__half2*)&rv.x);
            float2 f1 = __half22float2(*(__half2*)&rv.y);
            float2 f2 = __half22float2(*(__half2*)&rv.z);
            float2 f3 = __half22float2(*(__half2*)&rv.w);
            a0 += f0.x; a1 += f0.y; a2 += f1.x; a3 += f1.y;
            a4 += f2.x; a5 += f2.y; a6 += f3.x; a7 += f3.y;
        }
    }
    float sc = deinv_of(cnte);
    if (t == 0) g_t1[e] = sc * at;
    __half2 h0 = __floats2half2_rn(sc * a0, sc * a1);
    __half2 h1 = __floats2half2_rn(sc * a2, sc * a3);
    __half2 h2 = __floats2half2_rn(sc * a4, sc * a5);
    __half2 h3 = __floats2half2_rn(sc * a6, sc * a7);
    uint4 o;
    o.x = *(unsigned*)&h0; o.y = *(unsigned*)&h1;
    o.z = *(unsigned*)&h2; o.w = *(unsigned*)&h3;
    *(uint4*)&g_zh[(size_t)e * CH + t * 8] = o;
}

// ---------------- edge GEMM via wmma: z2h = zh @ blockdiag(W1h[b]) ----------------
// Tile M=128 x N=64; __launch_bounds__(256,3) -> 3 blocks/SM (verified: 60 us, occ 34.5%).
__global__ void __launch_bounds__(256, 3) k_egemm() {
    __shared__ __align__(16) union {
        struct { __half A[128][72]; __half B[64][72]; } in;   // 18432 + 9216 = 27648
        float Cf[8][32 * 36];                                  // 36864
    } sm;
    int t = threadIdx.x;
    int warp = t >> 5, lane = t & 31;
    int wm = warp >> 1, wn = warp & 1;
    int b = blockIdx.z;
    int row0 = blockIdx.x * 128;
    int col0 = blockIdx.y * 64;

    wmma::fragment<wmma::accumulator, 16, 16, 16, float> acc[2][2];
    #pragma unroll
    for (int i = 0; i < 2; i++)
        #pragma unroll
        for (int j = 0; j < 2; j++) wmma::fill_fragment(acc[i][j], 0.f);

    for (int kp = 0; kp < 256; kp += 64) {
        __syncthreads();
        #pragma unroll
        for (int i = 0; i < 4; i++) {   // A: 128x64 halfs = 1024 uint4 groups
            int g = t + 256 * i;
            int row = g >> 3, gc = (g & 7) * 8;
            int r = row0 + row;
            uint4 val = make_uint4(0u, 0u, 0u, 0u);
            if (r < NE) val = *(const uint4*)&g_zh[(size_t)r * CH + b * 256 + kp + gc];
            *(uint4*)&sm.in.A[row][gc] = val;
        }
        #pragma unroll
        for (int i = 0; i < 2; i++) {   // B: 64x64 halfs = 512 uint4 groups
            int g = t + 256 * i;
            int row = g >> 3, gc = (g & 7) * 8;
            *(uint4*)&sm.in.B[row][gc] =
                *(const uint4*)&g_W1h[b * 65536 + (kp + row) * 256 + col0 + gc];
        }
        __syncthreads();
        #pragma unroll
        for (int ks = 0; ks < 4; ks++) {
            wmma::fragment<wmma::matrix_a, 16, 16, 16, __half, wmma::row_major> af[2];
            wmma::fragment<wmma::matrix_b, 16, 16, 16, __half, wmma::row_major> bf[2];
            wmma::load_matrix_sync(af[0], &sm.in.A[wm * 32][ks * 16], 72);
            wmma::load_matrix_sync(af[1], &sm.in.A[wm * 32 + 16][ks * 16], 72);
            wmma::load_matrix_sync(bf[0], &sm.in.B[ks * 16][wn * 32], 72);
            wmma::load_matrix_sync(bf[1], &sm.in.B[ks * 16][wn * 32 + 16], 72);
            #pragma unroll
            for (int i = 0; i < 2; i++)
                #pragma unroll
                for (int j = 0; j < 2; j++)
                    wmma::mma_sync(acc[i][j], af[i], bf[j], acc[i][j]);
        }
    }
    __syncthreads();   // union reuse: all mma smem reads complete
    #pragma unroll
    for (int i = 0; i < 2; i++)
        #pragma unroll
        for (int j = 0; j < 2; j++)
            wmma::store_matrix_sync(&sm.Cf[warp][(i * 16) * 36 + j * 16], acc[i][j], 36,
                                    wmma::mem_row_major);
    __syncwarp();
    int gr = row0 + wm * 32 + lane;
    if (gr < NE) {
        size_t base = (size_t)gr * CH + b * 256 + col0 + wn * 32;
        const float* cr = &sm.Cf[warp][lane * 36];
        #pragma unroll
        for (int g4 = 0; g4 < 4; g4++) {
            float4 v0 = *(const float4*)&cr[g4 * 8];
            float4 v1 = *(const float4*)&cr[g4 * 8 + 4];
            __half2 h0 = __floats2half2_rn(v0.x, v0.y);
            __half2 h1 = __floats2half2_rn(v0.z, v0.w);
            __half2 h2 = __floats2half2_rn(v1.x, v1.y);
            __half2 h3 = __floats2half2_rn(v1.z, v1.w);
            uint4 o;
            o.x = *(unsigned*)&h0; o.y = *(unsigned*)&h1;
            o.z = *(unsigned*)&h2; o.w = *(unsigned*)&h3;
            *(uint4*)&g_z2h[base + g4 * 8] = o;
        }
    }
}

// ---------------- pass B: hiddenh[v][:] = relu(dv_is[v]*sum z2h + s[v]*b1[:]); s inline ----------------
__global__ void __launch_bounds__(128, 16) k_passB(const float* __restrict__ b1) {
    __shared__ int   see[128];
    __shared__ float st1[128];
    int v = blockIdx.x, t = threadIdx.x;
    int beg = v * PADN;
    int cntv = g_cnt_v[v];
    int deg = min(cntv, PADN);
    const __half* zb = g_z2h + t * 8;
    float a0 = 0.f, a1 = 0.f, a2 = 0.f, a3 = 0.f, a4 = 0.f, a5 = 0.f, a6 = 0.f, a7 = 0.f;
    float at = 0.f;
    for (int base = 0; base < deg; base += 128) {
        int m = min(128, deg - base);
        __syncthreads();
        if (t < m) {
            int ee = g_nlist[beg + base + t];
            see[t] = ee;
            st1[t] = g_t1[ee];
        }
        __syncthreads();
        #pragma unroll 8
        for (int i = 0; i < m; i++) {
            at += st1[i];
            uint4 rv = *(const uint4*)(zb + (size_t)see[i] * CH);
            float2 f0 = __half22float2(*(__half2*)&rv.x);
            float2 f1 = __half22float2(*(__half2*)&rv.y);
            float2 f2 = __half22float2(*(__half2*)&rv.z);
            float2 f3 = __half22float2(*(__half2*)&rv.w);
            a0 += f0.x; a1 += f0.y; a2 += f1.x; a3 += f1.y;
            a4 += f2.x; a5 += f2.y; a6 += f3.x; a7 += f3.y;
        }
    }
    float w = dvis_of(cntv);
    float sv = w * at;   // s[v] = dvis[v] * sum t1
    int c = t * 8;
    float4 bb0 = *(const float4*)&b1[c];
    float4 bb1 = *(const float4*)&b1[c + 4];
    float r0 = fmaxf(w * a0 + sv * bb0.x, 0.f);
    float r1 = fmaxf(w * a1 + sv * bb0.y, 0.f);
    float r2 = fmaxf(w * a2 + sv * bb0.z, 0.f);
    float r3 = fmaxf(w * a3 + sv * bb0.w, 0.f);
    float r4 = fmaxf(w * a4 + sv * bb1.x, 0.f);
    float r5 = fmaxf(w * a5 + sv * bb1.y, 0.f);
    float r6 = fmaxf(w * a6 + sv * bb1.z, 0.f);
    float r7 = fmaxf(w * a7 + sv * bb1.w, 0.f);
    __half2 h0 = __floats2half2_rn(r0, r1);
    __half2 h1 = __floats2half2_rn(r2, r3);
    __half2 h2 = __floats2half2_rn(r4, r5);
    __half2 h3 = __floats2half2_rn(r6, r7);
    uint4 o;
    o.x = *(unsigned*)&h0; o.y = *(unsigned*)&h1;
    o.z = *(unsigned*)&h2; o.w = *(unsigned*)&h3;
    *(uint4*)&g_hiddenh[(size_t)v * CH + c] = o;
}

// ---------------- GEMM2 via wmma: gvh = fp16(dvis * (hiddenh @ W2h + b2)) ----------------
__global__ void k_gemm2(const float* __restrict__ b2) {
    __shared__ __align__(16) union {
        struct { __half A[128][72]; __half B[64][56]; } in;   // 18432 + 7168
        float C[8][832];                                       // 26624
    } sm;
    int t = threadIdx.x;
    int warp = t >> 5, lane = t & 31;
    int row0 = blockIdx.x * 128;

    wmma::fragment<wmma::accumulator, 16, 16, 16, float> acc[3];
    #pragma unroll
    for (int j = 0; j < 3; j++) wmma::fill_fragment(acc[j], 0.f);

    for (int kp = 0; kp < CH; kp += 64) {
        __syncthreads();
        #pragma unroll
        for (int i = 0; i < 4; i++) {   // A: 128x64
            int g = t + 256 * i;
            int row = g >> 3, gc = (g & 7) * 8;
            int r = row0 + row;
            uint4 val = make_uint4(0u, 0u, 0u, 0u);
            if (r < NN) val = *(const uint4*)&g_hiddenh[(size_t)r * CH + kp + gc];
            *(uint4*)&sm.in.A[row][gc] = val;
        }
        #pragma unroll
        for (int i = 0; i < 2; i++) {   // B: 64x48 halfs = 384 uint4 groups
            int g = t + 256 * i;
            if (g < 384) {
                int row = g / 6, gc = (g % 6) * 8;
                *(uint4*)&sm.in.B[row][gc] = *(const uint4*)&g_W2h[(kp + row) * 48 + gc];
            }
        }
        __syncthreads();
        #pragma unroll
        for (int ks = 0; ks < 4; ks++) {
            wmma::fragment<wmma::matrix_a, 16, 16, 16, __half, wmma::row_major> af;
            wmma::load_matrix_sync(af, &sm.in.A[warp * 16][ks * 16], 72);
            #pragma unroll
            for (int j = 0; j < 3; j++) {
                wmma::fragment<wmma::matrix_b, 16, 16, 16, __half, wmma::row_major> bf;
                wmma::load_matrix_sync(bf, &sm.in.B[ks * 16][j * 16], 56);
                wmma::mma_sync(acc[j], af, bf, acc[j]);
            }
        }
    }
    __syncthreads();
    #pragma unroll
    for (int j = 0; j < 3; j++)
        wmma::store_matrix_sync(&sm.C[warp][j * 16], acc[j], 52, wmma::mem_row_major);
    __syncwarp();
    if (lane < 16) {
        int gr = row0 + warp * 16 + lane;
        if (gr < NN) {
            float w = dvis_of(g_cnt_v[gr]);
            const float* cr = &sm.C[warp][lane * 52];
            #pragma unroll
            for (int g4 = 0; g4 < 10; g4++) {
                float4 c0 = *(const float4*)&cr[g4 * 4];
                float4 d0 = *(const float4*)&b2[g4 * 4];
                __half2 h0 = __floats2half2_rn(w * (c0.x + d0.x), w * (c0.y + d0.y));
                __half2 h1 = __floats2half2_rn(w * (c0.z + d0.z), w * (c0.w + d0.w));
                uint2 o;
                o.x = *(unsigned*)&h0; o.y = *(unsigned*)&h1;
                *(uint2*)&g_gvh[(size_t)gr * COUT + g4 * 4] = o;
            }
        }
    }
}

// ---------------- final smooth on [N,40], fp16 tables ----------------
__global__ void k_passCe() {
    __shared__ float red[24][44];
    int e = blockIdx.x, t = threadIdx.x;
    int beg = e * PADE;
    int cnte = g_cnt_e[e];
    int deg = min(cnte, PADE);
    if (t < 240) {
        int r = t / 10, cg = (t % 10) * 4;
        float4 acc = make_float4(0.f, 0.f, 0.f, 0.f);
        for (int i = r; i < deg; i += 24) {
            int vv = g_elist[beg + i];
            uint2 gv = *(const uint2*)&g_gvh[(size_t)vv * COUT + cg];
            float2 f0 = __half22float2(*(__half2*)&gv.x);
            float2 f1 = __half22float2(*(__half2*)&gv.y);
            acc.x += f0.x; acc.y += f0.y; acc.z += f1.x; acc.w += f1.y;
        }
        *(float4*)&red[r][cg] = acc;
    }
    __syncthreads();
    if (t < 40) {
        float s = 0.f;
        #pragma unroll
        for (int r = 0; r < 24; r++) s += red[r][t];
        g_ef2h[(size_t)e * COUT + t] = __float2half_rn(deinv_of(cnte) * s);
    }
}
__global__ void k_passCn(float* __restrict__ out) {
    __shared__ float red[24][44];
    int v = blockIdx.x, t = threadIdx.x;
    int beg = v * PADN;
    int cntv = g_cnt_v[v];
    int deg = min(cntv, PADN);
    if (t < 240) {
        int r = t / 10, cg = (t % 10) * 4;
        float4 acc = make_float4(0.f, 0.f, 0.f, 0.f);
        for (int i = r; i < deg; i += 24) {
            int e = g_nlist[beg + i];
            uint2 ev = *(const uint2*)&g_ef2h[(size_t)e * COUT + cg];
            float2 f0 = __half22float2(*(__half2*)&ev.x);
            float2 f1 = __half22float2(*(__half2*)&ev.y);
            acc.x += f0.x; acc.y += f0.y; acc.z += f1.x; acc.w += f1.y;
        }
        *(float4*)&red[r][cg] = acc;
    }
    __syncthreads();
    if (t < 40) {
        float s = 0.f;
        #pragma unroll
        for (int r = 0; r < 24; r++) s += red[r][t];
        out[(size_t)v * COUT + t] = dvis_of(cntv) * s;
    }
}

// ---------------- launch ----------------
extern "C" void kernel_launch(void* const* d_in, const int* in_sizes, int n_in,
                              void* d_out, int out_size) {
    const float* x  = (const float*)d_in[0];   // [4, NN, 256]
    const float* W1 = (const float*)d_in[1];   // [4, 256, 256]
    const float* b1 = (const float*)d_in[2];   // [4, 256] -> flat [1024]
    const float* W2 = (const float*)d_in[3];   // [1024, 40]
    const float* b2 = (const float*)d_in[4];   // [40]
    const int*   ni = (const int*)d_in[5];     // node_idx [NNZ]
    const int*   ei = (const int*)d_in[6];     // edge_idx [NNZ]
    int nnz = in_sizes[5];
    float* out = (float*)d_out;

    k_zero  <<<(NN + 255) / 256, 256>>>();                    // (1) tiny
    k_fill  <<<(nnz + 255) / 256, 256>>>(ni, ei, nnz);        // (2) atomics on clean L2
    k_cvt   <<<(CVT_W2_T + 255) / 256, 256>>>(x, W1, W2);     // (3) prescaled; xh L2-warm
    k_passA <<<NE, 128>>>();                                  // (4) <- ncu window
    {
        dim3 grid((NE + 127) / 128, 4, 4);
        k_egemm<<<grid, 256>>>();
    }
    k_passB <<<NN, 128>>>(b1);
    k_gemm2 <<<(NN + 127) / 128, 256>>>(b2);
    k_passCe<<<NE, 256>>>();
    k_passCn<<<NN, 256>>>(out);
}